// round 2
// baseline (speedup 1.0000x reference)
#include <cuda_runtime.h>
#include <cuda_bf16.h>
#include <cstdint>

typedef unsigned long long ull;

#define BSZ   256
#define LSEQ  2048
#define DD    128   // DIN == DOUT == 128

// ---------------------------------------------------------------------------
// Scratch for the three x-projections (U includes u_b, Gx includes g_b).
// __device__ globals: the sanctioned alloc-free scratch mechanism.
// ---------------------------------------------------------------------------
__device__ float d_U [BSZ * LSEQ * DD];
__device__ float d_Gx[BSZ * LSEQ * DD];
__device__ float d_Ax[BSZ * LSEQ * DD];

// ---------------------------------------------------------------------------
// f32x2 helpers (FFMA2: 2 fp32 FMA per instruction on sm_103a)
// ---------------------------------------------------------------------------
__device__ __forceinline__ ull pk2(float x, float y) {
    ull r;
    asm("mov.b64 %0, {%1, %2};" : "=l"(r) : "f"(x), "f"(y));
    return r;
}
__device__ __forceinline__ float2 upk2(ull v) {
    float2 f;
    asm("mov.b64 {%0, %1}, %2;" : "=f"(f.x), "=f"(f.y) : "l"(v));
    return f;
}
__device__ __forceinline__ ull ffma2(ull a, ull b, ull c) {
    ull d;
    asm("fma.rn.f32x2 %0, %1, %2, %3;" : "=l"(d) : "l"(a), "l"(b), "l"(c));
    return d;
}

__device__ __forceinline__ float tanhf_fast(float x) {
    float ax = fabsf(x);
    float e  = __expf(-2.0f * ax);
    float r  = __fdividef(1.0f - e, 1.0f + e);
    return copysignf(r, x);
}

// ---------------------------------------------------------------------------
// Projection GEMM: C[row, o] = sum_d x[row, d] * W[o, d]  (+ bias)
//   row = b*L + t  (x is row-major [B*L, 128])
//   blockIdx.y selects the matrix: 0 -> u_w (pitch 128, +u_b)
//                                  1 -> g_w[:, :128] (pitch 256, +g_b)
//                                  2 -> a_w[:, :128] (pitch 256, no bias)
// Tile: 128(M) x 128(N) x 128(K), 256 threads, 8x8 micro-tile,
// K packed in f32x2 pairs. B tile XOR-swizzled for conflict-free LDS.64.
// ---------------------------------------------------------------------------
__global__ void __launch_bounds__(256, 1)
rwa_proj_kernel(const float* __restrict__ x,
                const float* __restrict__ u_w,
                const float* __restrict__ u_b,
                const float* __restrict__ g_w,
                const float* __restrict__ g_b,
                const float* __restrict__ a_w)
{
    extern __shared__ ull smem[];
    ull* Asm = smem;          // [128][64] float2 : Asm[m*64 + k2]
    ull* Bsm = smem + 8192;   // [128][64] float2 : Bsm[n*64 + (k2 ^ (n&15))]

    const int tid = threadIdx.x;
    const int tx  = tid & 15;     // -> n = tx + jj*16
    const int ty  = tid >> 4;     // -> m = ty + ii*16
    const int nt  = blockIdx.y;
    const int row0 = blockIdx.x * 128;

    const float* wsrc = (nt == 0) ? u_w : (nt == 1) ? g_w : a_w;
    const int    wpitch = (nt == 0) ? 128 : 256;

    // ---- load A tile (x rows), store as float2 pairs along K ----
    {
        const float4* xp = (const float4*)(x + (size_t)row0 * DD);
        #pragma unroll
        for (int i = 0; i < 16; i++) {
            int idx = tid + i * 256;
            int r  = idx >> 5;
            int c4 = idx & 31;           // float4 index within row
            float4 v = xp[(size_t)r * 32 + c4];
            Asm[r * 64 + c4 * 2    ] = pk2(v.x, v.y);
            Asm[r * 64 + c4 * 2 + 1] = pk2(v.z, v.w);
        }
    }
    // ---- load B tile (weights), swizzled ----
    {
        #pragma unroll
        for (int i = 0; i < 16; i++) {
            int idx = tid + i * 256;
            int n  = idx >> 5;
            int c4 = idx & 31;
            const float4* wp = (const float4*)(wsrc + (size_t)n * wpitch);
            float4 v = wp[c4];
            int sw = n & 15;
            Bsm[n * 64 + ((c4 * 2    ) ^ sw)] = pk2(v.x, v.y);
            Bsm[n * 64 + ((c4 * 2 + 1) ^ sw)] = pk2(v.z, v.w);
        }
    }
    __syncthreads();

    ull acc[8][8];
    #pragma unroll
    for (int ii = 0; ii < 8; ii++)
        #pragma unroll
        for (int jj = 0; jj < 8; jj++) acc[ii][jj] = 0ull;

    #pragma unroll 4
    for (int k2 = 0; k2 < 64; k2++) {
        ull af[8], bf[8];
        #pragma unroll
        for (int ii = 0; ii < 8; ii++)
            af[ii] = Asm[(ty + ii * 16) * 64 + k2];
        #pragma unroll
        for (int jj = 0; jj < 8; jj++)
            bf[jj] = Bsm[(tx + jj * 16) * 64 + (k2 ^ tx)];
        #pragma unroll
        for (int ii = 0; ii < 8; ii++)
            #pragma unroll
            for (int jj = 0; jj < 8; jj++)
                acc[ii][jj] = ffma2(af[ii], bf[jj], acc[ii][jj]);
    }

    // ---- epilogue: bias + store ----
    float bias[8];
    #pragma unroll
    for (int jj = 0; jj < 8; jj++) {
        int n = tx + jj * 16;
        bias[jj] = (nt == 0) ? u_b[n] : (nt == 1) ? g_b[n] : 0.0f;
    }
    float* dst = (nt == 0) ? d_U : (nt == 1) ? d_Gx : d_Ax;

    #pragma unroll
    for (int ii = 0; ii < 8; ii++) {
        size_t rbase = (size_t)(row0 + ty + ii * 16) * DD;
        #pragma unroll
        for (int jj = 0; jj < 8; jj++) {
            float2 s = upk2(acc[ii][jj]);
            dst[rbase + tx + jj * 16] = s.x + s.y + bias[jj];
        }
    }
}

// ---------------------------------------------------------------------------
// Recurrent kernel: 128 CTAs x 512 threads; CTA handles batches (2*bid, 2*bid+1).
// Thread (o = tid&127, q = tid>>7) holds g_wh[o][32q..32q+31] and
// a_wh[o][...] in registers; per step computes partial h-matvecs for both
// batches, reduces via smem; threads tid<256 run the activation epilogue
// holding (num, den, a_max) in registers, prefetching U/Gx/Ax one step ahead.
// ---------------------------------------------------------------------------
__global__ void __launch_bounds__(512, 1)
rwa_rec_kernel(const float* __restrict__ g_w,
               const float* __restrict__ a_w,
               const float* __restrict__ s0,
               float* __restrict__ out)
{
    __shared__ ull   hsm[2 * 64];          // h as float2 pairs: [b][64]
    __shared__ float partG[4 * 2 * DD];    // [q][b][o]
    __shared__ float partA[4 * 2 * DD];

    const int tid = threadIdx.x;
    const int o   = tid & 127;
    const int q   = tid >> 7;

    // h-recurrence weights (cols 128..255 of g_w / a_w), in registers
    ull wg[16], wa[16];
    {
        const ull* gp = (const ull*)(g_w + (size_t)o * 256 + 128 + q * 32);
        const ull* ap = (const ull*)(a_w + (size_t)o * 256 + 128 + q * 32);
        #pragma unroll
        for (int j = 0; j < 16; j++) { wg[j] = gp[j]; wa[j] = ap[j]; }
    }

    const int eb = tid >> 7;   // epilogue batch (valid when tid < 256)
    const int eo = o;
    float num = 0.0f, den = 0.0f, amax = 1e-38f;
    size_t idx0 = ((size_t)(blockIdx.x * 2 + eb)) * LSEQ * DD + eo;
    float u_n = 0.0f, gx_n = 0.0f, ax_n = 0.0f;

    if (tid < 256) {
        ((float*)hsm)[eb * DD + eo] = tanhf_fast(s0[eo]);
        u_n  = d_U [idx0];
        gx_n = d_Gx[idx0];
        ax_n = d_Ax[idx0];
    }
    __syncthreads();

    const ull* h0p = hsm + q * 16;        // batch 0, this thread's d-quarter
    const ull* h1p = hsm + 64 + q * 16;   // batch 1

    for (int t = 0; t < LSEQ; t++) {
        // ---- h-matvec partials (all 512 threads, both batches) ----
        ull aG0 = 0ull, aA0 = 0ull, aG1 = 0ull, aA1 = 0ull;
        #pragma unroll
        for (int j = 0; j < 16; j++) {
            ull h0 = h0p[j];
            ull h1 = h1p[j];
            aG0 = ffma2(wg[j], h0, aG0);
            aA0 = ffma2(wa[j], h0, aA0);
            aG1 = ffma2(wg[j], h1, aG1);
            aA1 = ffma2(wa[j], h1, aA1);
        }
        {
            float2 s;
            s = upk2(aG0); partG[q * 256 +       o] = s.x + s.y;
            s = upk2(aG1); partG[q * 256 + 128 + o] = s.x + s.y;
            s = upk2(aA0); partA[q * 256 +       o] = s.x + s.y;
            s = upk2(aA1); partA[q * 256 + 128 + o] = s.x + s.y;
        }
        __syncthreads();

        // ---- activation epilogue (256 threads: one per (b, o)) ----
        if (tid < 256) {
            int pb = eb * DD + eo;
            float sumG = partG[pb] + partG[256 + pb] + partG[512 + pb] + partG[768 + pb];
            float sumA = partA[pb] + partA[256 + pb] + partA[512 + pb] + partA[768 + pb];

            float u = u_n, gx = gx_n, ax = ax_n;
            if (t + 1 < LSEQ) {                       // prefetch next step
                size_t id = idx0 + (size_t)(t + 1) * DD;
                u_n  = d_U [id];
                gx_n = d_Gx[id];
                ax_n = d_Ax[id];
            }

            float g  = tanhf_fast(gx + sumG);
            float z  = u * g;
            float a  = ax + sumA;
            float am = fmaxf(a, amax);
            float e  = __expf(am - amax);
            amax = am;
            num  = fmaf(z, e, num);
            den += e;
            float h = tanhf_fast(__fdividef(num, den));

            ((float*)hsm)[eb * DD + eo] = h;
            out[idx0 + (size_t)t * DD] = h;
        }
        __syncthreads();
    }
}

// ---------------------------------------------------------------------------
// kernel_launch
// Input order (metadata): 0:x  1:s0  2:u_w  3:u_b  4:g_w  5:g_b  6:a_w
// ---------------------------------------------------------------------------
extern "C" void kernel_launch(void* const* d_in, const int* in_sizes, int n_in,
                              void* d_out, int out_size)
{
    const float* x   = (const float*)d_in[0];
    const float* s0  = (const float*)d_in[1];
    const float* u_w = (const float*)d_in[2];
    const float* u_b = (const float*)d_in[3];
    const float* g_w = (const float*)d_in[4];
    const float* g_b = (const float*)d_in[5];
    const float* a_w = (const float*)d_in[6];
    float* out = (float*)d_out;

    cudaFuncSetAttribute(rwa_proj_kernel,
                         cudaFuncAttributeMaxDynamicSharedMemorySize, 131072);

    dim3 pgrid((BSZ * LSEQ) / 128, 3, 1);
    rwa_proj_kernel<<<pgrid, 256, 131072>>>(x, u_w, u_b, g_w, g_b, a_w);

    rwa_rec_kernel<<<BSZ / 2, 512>>>(g_w, a_w, s0, out);
}